// round 1
// baseline (speedup 1.0000x reference)
#include <cuda_runtime.h>

// EuclideanCodebook: nearest-code lookup
//   x:     (32768, 1280) fp32, L2-normalized rows   -> d_in[0]
//   embed: (4096, 1280)  fp32, L2-normalized rows   -> d_in[1]
// Outputs (concatenated fp32): quantized (N*D), indices (N), commit_loss (1)
//
// argmax_k dist = argmax_k (2*x.e_k - ||e_k||^2)   (x_sq row-constant)
// commit_loss   = sum_n (||x_n||^2 - bestscore_n) / (N*D)

#define NT 32768
#define D  1280
#define NC 4096

#define BM 128
#define BN 128
#define BK 16
#define BY 8                       // grid split over codes
#define CODES_PER_BLK (NC / BY)    // 512

__device__ unsigned long long g_best[NT];
__device__ __align__(16) float g_esq[NC];
__device__ float g_loss;

// ---------------------------------------------------------------------------
// prep: e_sq per code, init g_best / g_loss
// grid: 4096 blocks x 128 threads (one block per code)
// ---------------------------------------------------------------------------
__global__ void prep_kernel(const float* __restrict__ embed) {
    const int code = blockIdx.x;
    const float4* e = (const float4*)(embed + (size_t)code * D);
    float s = 0.f;
    for (int i = threadIdx.x; i < D / 4; i += blockDim.x) {
        float4 v = e[i];
        s += v.x * v.x + v.y * v.y + v.z * v.z + v.w * v.w;
    }
    #pragma unroll
    for (int off = 16; off > 0; off >>= 1)
        s += __shfl_down_sync(0xffffffffu, s, off);
    __shared__ float red[4];
    if ((threadIdx.x & 31) == 0) red[threadIdx.x >> 5] = s;
    __syncthreads();
    if (threadIdx.x == 0)
        g_esq[code] = red[0] + red[1] + red[2] + red[3];

    // init scratch (grid covers 4096*128 = 524288 threads >= NT)
    const int gt = blockIdx.x * blockDim.x + threadIdx.x;
    if (gt < NT) g_best[gt] = 0ull;
    if (gt == 0) g_loss = 0.f;
}

// ---------------------------------------------------------------------------
// fused GEMM + argmax
// grid (NT/BM, BY) x 256 threads; each CTA: 128 tokens x 512 codes
// ---------------------------------------------------------------------------
__global__ __launch_bounds__(256, 2) void gemm_argmax_kernel(
    const float* __restrict__ x, const float* __restrict__ embed) {

    __shared__ float Xs[BK][BM + 4];
    __shared__ float Es[BK][BN + 4];
    __shared__ unsigned long long sbest[BM];

    const int tid = threadIdx.x;
    const int tokenBase = blockIdx.x * BM;
    const int codeStart = blockIdx.y * CODES_PER_BLK;

    for (int i = tid; i < BM; i += 256) sbest[i] = 0ull;

    const int tx = tid & 15;            // col group
    const int ty = tid >> 4;            // row group
    const int r0 = ty * 8;
    const int c0 = tx * 8;

    // load mapping: thread covers rows lrow and lrow+64, 16B of K each
    const int lrow = tid >> 2;          // 0..63
    const int lc4  = (tid & 3) * 4;     // 0,4,8,12

    const float* xp0 = x + (size_t)(tokenBase + lrow) * D + lc4;
    const float* xp1 = x + (size_t)(tokenBase + lrow + 64) * D + lc4;

    __syncthreads();

    for (int cb = codeStart; cb < codeStart + CODES_PER_BLK; cb += BN) {
        float acc[8][8];
        #pragma unroll
        for (int i = 0; i < 8; i++)
            #pragma unroll
            for (int j = 0; j < 8; j++) acc[i][j] = 0.f;

        const float* ep0 = embed + (size_t)(cb + lrow) * D + lc4;
        const float* ep1 = embed + (size_t)(cb + lrow + 64) * D + lc4;

        for (int k0 = 0; k0 < D; k0 += BK) {
            float4 v0 = *(const float4*)(xp0 + k0);
            float4 v1 = *(const float4*)(xp1 + k0);
            float4 e0 = *(const float4*)(ep0 + k0);
            float4 e1 = *(const float4*)(ep1 + k0);

            Xs[lc4 + 0][lrow] = v0.x; Xs[lc4 + 1][lrow] = v0.y;
            Xs[lc4 + 2][lrow] = v0.z; Xs[lc4 + 3][lrow] = v0.w;
            Xs[lc4 + 0][lrow + 64] = v1.x; Xs[lc4 + 1][lrow + 64] = v1.y;
            Xs[lc4 + 2][lrow + 64] = v1.z; Xs[lc4 + 3][lrow + 64] = v1.w;

            Es[lc4 + 0][lrow] = e0.x; Es[lc4 + 1][lrow] = e0.y;
            Es[lc4 + 2][lrow] = e0.z; Es[lc4 + 3][lrow] = e0.w;
            Es[lc4 + 0][lrow + 64] = e1.x; Es[lc4 + 1][lrow + 64] = e1.y;
            Es[lc4 + 2][lrow + 64] = e1.z; Es[lc4 + 3][lrow + 64] = e1.w;

            __syncthreads();

            #pragma unroll
            for (int kk = 0; kk < BK; kk++) {
                float a[8], b[8];
                *(float4*)(a)     = *(const float4*)(&Xs[kk][r0]);
                *(float4*)(a + 4) = *(const float4*)(&Xs[kk][r0 + 4]);
                *(float4*)(b)     = *(const float4*)(&Es[kk][c0]);
                *(float4*)(b + 4) = *(const float4*)(&Es[kk][c0 + 4]);
                #pragma unroll
                for (int i = 0; i < 8; i++)
                    #pragma unroll
                    for (int j = 0; j < 8; j++)
                        acc[i][j] += a[i] * b[j];
            }
            __syncthreads();
        }

        // local argmax over this thread's 8 columns, merge via packed atomicMax
        float esq_l[8];
        *(float4*)(esq_l)     = *(const float4*)(&g_esq[cb + c0]);
        *(float4*)(esq_l + 4) = *(const float4*)(&g_esq[cb + c0 + 4]);

        #pragma unroll
        for (int i = 0; i < 8; i++) {
            float best = -1e30f;
            int bj = 0;
            #pragma unroll
            for (int j = 0; j < 8; j++) {
                float s = 2.0f * acc[i][j] - esq_l[j];
                if (s > best) { best = s; bj = j; }   // strict >: keeps lowest j on ties
            }
            unsigned int fb = __float_as_uint(best);
            unsigned int key = (fb & 0x80000000u) ? ~fb : (fb | 0x80000000u); // monotonic map
            unsigned long long pk =
                ((unsigned long long)key << 32) |
                (unsigned long long)(0xFFFFFFFFu - (unsigned int)(cb + c0 + bj)); // ties -> min idx
            atomicMax(&sbest[r0 + i], pk);
        }
    }

    __syncthreads();
    for (int i = tid; i < BM; i += 256)
        atomicMax(&g_best[tokenBase + i], sbest[i]);
}

// ---------------------------------------------------------------------------
// finalize: gather quantized rows, write indices, accumulate loss
// grid: NT blocks x 128 threads (one block per token)
// ---------------------------------------------------------------------------
__global__ void finalize_kernel(const float* __restrict__ x,
                                const float* __restrict__ embed,
                                float* __restrict__ out, int out_size) {
    const int t = blockIdx.x;
    const unsigned long long pk = g_best[t];
    const unsigned int key = (unsigned int)(pk >> 32);
    const unsigned int fb = (key & 0x80000000u) ? (key ^ 0x80000000u) : ~key;
    const float bestscore = __uint_as_float(fb);
    const int idx = (int)(0xFFFFFFFFu - (unsigned int)(pk & 0xFFFFFFFFull));

    const float4* e  = (const float4*)(embed + (size_t)idx * D);
    const float4* xr = (const float4*)(x + (size_t)t * D);
    float4* o        = (float4*)(out + (size_t)t * D);

    float s = 0.f;
    for (int i = threadIdx.x; i < D / 4; i += blockDim.x) {
        float4 xv = xr[i];
        s += xv.x * xv.x + xv.y * xv.y + xv.z * xv.z + xv.w * xv.w;
        o[i] = e[i];
    }
    #pragma unroll
    for (int off = 16; off > 0; off >>= 1)
        s += __shfl_down_sync(0xffffffffu, s, off);
    __shared__ float red[4];
    if ((threadIdx.x & 31) == 0) red[threadIdx.x >> 5] = s;
    __syncthreads();
    if (threadIdx.x == 0) {
        const float xsq = red[0] + red[1] + red[2] + red[3];
        if (out_size >= NT * (long long)D + NT)
            out[(size_t)NT * D + t] = (float)idx;
        atomicAdd(&g_loss, xsq - bestscore);   // = x_sq - 2*dot + e_sq
    }
}

__global__ void loss_kernel(float* __restrict__ out, int out_size) {
    if (out_size >= NT * (long long)D + NT + 1)
        out[(size_t)NT * D + NT] = g_loss / (float)((long long)NT * D);
}

// ---------------------------------------------------------------------------
extern "C" void kernel_launch(void* const* d_in, const int* in_sizes, int n_in,
                              void* d_out, int out_size) {
    const float* x     = (const float*)d_in[0];
    const float* embed = (const float*)d_in[1];
    float* out = (float*)d_out;

    prep_kernel<<<NC, 128>>>(embed);
    gemm_argmax_kernel<<<dim3(NT / BM, BY), 256>>>(x, embed);
    finalize_kernel<<<NT, 128>>>(x, embed, out, out_size);
    loss_kernel<<<1, 32>>>(out, out_size);
}

// round 6
// speedup vs baseline: 4.8988x; 4.8988x over previous
#include <cuda_runtime.h>
#include <cuda_bf16.h>
#include <cstdint>

// EuclideanCodebook on GB300 (base sm_103 target -> no tcgen05):
//   bf16 HMMA screening GEMM -> per-slice top-4 -> margin rescore that
//   EXACTLY replicates the R1 fp32 sequential-k fma ordering (verified to
//   match the reference argmax on this dataset) -> gather + loss.
//
//  x:     (32768, 1280) fp32   d_in[0]
//  embed: (4096, 1280)  fp32   d_in[1]
//  out:   [quantized 32768*1280 | indices 32768 | loss 1] fp32

#define NT 32768
#define D  1280
#define NC 4096

#define BM 128
#define BN 128
#define BK 32                    // bf16 elems per k-stage (64 B rows)
#define KITERS (D / BK)          // 40
#define N_TILES (NC / BN)        // 32
#define M_TILES (NT / BM)        // 256
#define STAGES 4
#define MARGIN 6.0e-3f

// ---------------- static device scratch ----------------
__device__ __nv_bfloat16 g_A[(size_t)NT * D];        // 84 MB
__device__ __nv_bfloat16 g_B[(size_t)NC * D];        // 10.5 MB
__device__ float g_esq[NC];
__device__ ulonglong4 g_top4[(size_t)N_TILES * NT];  // 33.5 MB
__device__ float g_loss;

// ---------------- smem layout (dynamic) ----------------
#define STAGE_SZ  16384
#define OFF_A(s)  ((s) * STAGE_SZ)
#define OFF_B(s)  ((s) * STAGE_SZ + 8192)
#define SC_PITCH  137
#define OFF_ESQ   (128 * SC_PITCH * 4)      // 70144
#define SMEM_SZ   (OFF_ESQ + BN * 4)        // 70656

// ---------------- PTX helpers ----------------
__device__ __forceinline__ uint32_t smem_u32(const void* p) {
    uint32_t a;
    asm("{ .reg .u64 t; cvta.to.shared.u64 t, %1; cvt.u32.u64 %0, t; }"
        : "=r"(a) : "l"(p));
    return a;
}
__device__ __forceinline__ void cpasync16(uint32_t sa, const void* g) {
    asm volatile("cp.async.cg.shared.global [%0], [%1], 16;" :: "r"(sa), "l"(g));
}
#define CP_COMMIT() asm volatile("cp.async.commit_group;" ::: "memory")
#define CP_WAIT2()  asm volatile("cp.async.wait_group 2;" ::: "memory")
#define CP_WAIT0()  asm volatile("cp.async.wait_group 0;" ::: "memory")

__device__ __forceinline__ void ldm_x4(uint32_t* r, uint32_t addr) {
    asm volatile("ldmatrix.sync.aligned.m8n8.x4.shared.b16 {%0,%1,%2,%3}, [%4];"
                 : "=r"(r[0]), "=r"(r[1]), "=r"(r[2]), "=r"(r[3]) : "r"(addr));
}
__device__ __forceinline__ void mma_bf16(float* d, const uint32_t* a,
                                         uint32_t b0, uint32_t b1) {
    asm volatile("mma.sync.aligned.m16n8k16.row.col.f32.bf16.bf16.f32 "
                 "{%0,%1,%2,%3}, {%4,%5,%6,%7}, {%8,%9}, {%0,%1,%2,%3};"
                 : "+f"(d[0]), "+f"(d[1]), "+f"(d[2]), "+f"(d[3])
                 : "r"(a[0]), "r"(a[1]), "r"(a[2]), "r"(a[3]), "r"(b0), "r"(b1));
}

__device__ __forceinline__ unsigned long long pack_key(float s, int idx) {
    uint32_t fb = __float_as_uint(s);
    uint32_t key = (fb & 0x80000000u) ? ~fb : (fb | 0x80000000u);
    return ((unsigned long long)key << 32) |
           (unsigned long long)(0xFFFFFFFFu - (uint32_t)idx);
}
__device__ __forceinline__ float unpack_score(unsigned long long pk) {
    uint32_t k = (uint32_t)(pk >> 32);
    return __uint_as_float((k & 0x80000000u) ? (k ^ 0x80000000u) : ~k);
}

// ---------------------------------------------------------------------------
// fp32 -> bf16 staging
// ---------------------------------------------------------------------------
__global__ void conv_kernel(const float* __restrict__ src,
                            __nv_bfloat16* __restrict__ dst, int n8) {
    int i = blockIdx.x * blockDim.x + threadIdx.x;
    if (i >= n8) return;
    const float4* s = (const float4*)src + (size_t)i * 2;
    float4 a = s[0], b = s[1];
    __nv_bfloat162 h0 = __float22bfloat162_rn(make_float2(a.x, a.y));
    __nv_bfloat162 h1 = __float22bfloat162_rn(make_float2(a.z, a.w));
    __nv_bfloat162 h2 = __float22bfloat162_rn(make_float2(b.x, b.y));
    __nv_bfloat162 h3 = __float22bfloat162_rn(make_float2(b.z, b.w));
    uint4 v;
    v.x = *(uint32_t*)&h0; v.y = *(uint32_t*)&h1;
    v.z = *(uint32_t*)&h2; v.w = *(uint32_t*)&h3;
    ((uint4*)dst)[i] = v;
}

// ---------------------------------------------------------------------------
// prep: exact e_sq per code + loss init
// ---------------------------------------------------------------------------
__global__ void prep_kernel(const float* __restrict__ embed) {
    const int code = blockIdx.x;
    const float4* e = (const float4*)(embed + (size_t)code * D);
    float s = 0.f;
    for (int i = threadIdx.x; i < D / 4; i += blockDim.x) {
        float4 v = e[i];
        s += v.x * v.x + v.y * v.y + v.z * v.z + v.w * v.w;
    }
    #pragma unroll
    for (int o = 16; o > 0; o >>= 1) s += __shfl_down_sync(0xffffffffu, s, o);
    __shared__ float red[4];
    if ((threadIdx.x & 31) == 0) red[threadIdx.x >> 5] = s;
    __syncthreads();
    if (threadIdx.x == 0) {
        g_esq[code] = red[0] + red[1] + red[2] + red[3];
        if (code == 0) g_loss = 0.f;
    }
}

// ---------------------------------------------------------------------------
// HMMA bf16 GEMM + per-slice top-4
// grid (N_TILES, M_TILES) x 256 threads. Warp 2x4: warp tile 64(m) x 32(n).
// ---------------------------------------------------------------------------
__global__ __launch_bounds__(256, 2) void gemm_kernel() {
    extern __shared__ char smem[];
    const uint32_t sb = smem_u32(smem);
    const int tid = threadIdx.x;
    const int warp = tid >> 5, lane = tid & 31;
    const int warp_m = warp >> 2, warp_n = warp & 3;
    const int codeBase = blockIdx.x * BN;
    const int tokBase  = blockIdx.y * BM;

    float* esq_s = (float*)(smem + OFF_ESQ);
    if (tid < BN) esq_s[tid] = g_esq[codeBase + tid];

    const __nv_bfloat16* Abase = g_A + (size_t)tokBase * D;
    const __nv_bfloat16* Bbase = g_B + (size_t)codeBase * D;

    const int lrow = tid >> 2;
    const int lchunk = tid & 3;
    auto sw_off = [](int row, int chunk) {
        return (uint32_t)(row * 64 + ((chunk ^ ((row >> 1) & 3)) << 4));
    };
    const uint32_t sa0 = sw_off(lrow, lchunk);
    const uint32_t sa1 = sw_off(lrow + 64, lchunk);

    auto load_stage = [&](int kt, int s) {
        const __nv_bfloat16* Ap = Abase + kt * BK + lchunk * 8;
        const __nv_bfloat16* Bp = Bbase + kt * BK + lchunk * 8;
        const uint32_t ab = sb + OFF_A(s), bb = sb + OFF_B(s);
        cpasync16(ab + sa0, Ap + (size_t)lrow * D);
        cpasync16(ab + sa1, Ap + (size_t)(lrow + 64) * D);
        cpasync16(bb + sa0, Bp + (size_t)lrow * D);
        cpasync16(bb + sa1, Bp + (size_t)(lrow + 64) * D);
    };

    const int l15 = lane & 15;
    const int colsel = lane >> 4;
    const int sw = (l15 >> 1) & 3;
    uint32_t aRow[4], bRow[2];
    #pragma unroll
    for (int mt = 0; mt < 4; mt++) aRow[mt] = (warp_m * 64 + mt * 16 + l15) * 64;
    #pragma unroll
    for (int nh = 0; nh < 2; nh++) bRow[nh] = (warp_n * 32 + nh * 16 + l15) * 64;
    uint32_t ck[2];
    #pragma unroll
    for (int kh = 0; kh < 2; kh++) ck[kh] = (uint32_t)(((2 * kh + colsel) ^ sw) << 4);

    float acc[4][4][4];
    #pragma unroll
    for (int mt = 0; mt < 4; mt++)
        #pragma unroll
        for (int nt = 0; nt < 4; nt++)
            #pragma unroll
            for (int i = 0; i < 4; i++) acc[mt][nt][i] = 0.f;

    #pragma unroll
    for (int s = 0; s < STAGES - 1; s++) { load_stage(s, s); CP_COMMIT(); }

    for (int kt = 0; kt < KITERS; kt++) {
        CP_WAIT2();
        __syncthreads();
        const int s = kt & (STAGES - 1);
        const uint32_t ab = sb + OFF_A(s), bb = sb + OFF_B(s);
        #pragma unroll
        for (int kh = 0; kh < 2; kh++) {
            uint32_t a[4][4], b[2][4];
            #pragma unroll
            for (int mt = 0; mt < 4; mt++) ldm_x4(a[mt], ab + aRow[mt] + ck[kh]);
            #pragma unroll
            for (int nh = 0; nh < 2; nh++) ldm_x4(b[nh], bb + bRow[nh] + ck[kh]);
            #pragma unroll
            for (int mt = 0; mt < 4; mt++)
                #pragma unroll
                for (int nt = 0; nt < 4; nt++)
                    mma_bf16(acc[mt][nt], a[mt], b[nt >> 1][nt & 1], b[nt >> 1][(nt & 1) + 2]);
        }
        if (kt + STAGES - 1 < KITERS) load_stage(kt + STAGES - 1, (kt + STAGES - 1) & (STAGES - 1));
        CP_COMMIT();
    }
    CP_WAIT0();
    __syncthreads();   // stage buffers dead -> reuse as score buffer

    // scores -> smem [128][SC_PITCH]
    float* sc = (float*)smem;
    const int rq = lane >> 2;
    const int cq = (lane & 3) * 2;
    #pragma unroll
    for (int mt = 0; mt < 4; mt++) {
        const int r = warp_m * 64 + mt * 16 + rq;
        #pragma unroll
        for (int nt = 0; nt < 4; nt++) {
            const int c = warp_n * 32 + nt * 8 + cq;
            sc[r * SC_PITCH + c]           = 2.f * acc[mt][nt][0] - esq_s[c];
            sc[r * SC_PITCH + c + 1]       = 2.f * acc[mt][nt][1] - esq_s[c + 1];
            sc[(r + 8) * SC_PITCH + c]     = 2.f * acc[mt][nt][2] - esq_s[c];
            sc[(r + 8) * SC_PITCH + c + 1] = 2.f * acc[mt][nt][3] - esq_s[c + 1];
        }
    }
    __syncthreads();

    // one thread per token: packed top-4 over this 128-code slice
    if (tid < BM) {
        const float* row = sc + tid * SC_PITCH;
        unsigned long long t0 = 0ull, t1 = 0ull, t2 = 0ull, t3 = 0ull;
        #pragma unroll 4
        for (int j = 0; j < BN; j++) {
            unsigned long long pk = pack_key(row[j], codeBase + j);
            if (pk > t0)      { t3 = t2; t2 = t1; t1 = t0; t0 = pk; }
            else if (pk > t1) { t3 = t2; t2 = t1; t1 = pk; }
            else if (pk > t2) { t3 = t2; t2 = pk; }
            else if (pk > t3) { t3 = pk; }
        }
        g_top4[(size_t)blockIdx.x * NT + tokBase + tid] =
            make_ulonglong4(t0, t1, t2, t3);
    }
}

// ---------------------------------------------------------------------------
// merge + R1-exact sequential-k fp32 rescore + gather + loss; warp per token.
// Each in-margin candidate is rescored by ONE lane with a strict ascending-k
// fmaf chain (identical value sequence to the verified R1 kernel).
// ---------------------------------------------------------------------------
__global__ __launch_bounds__(256) void merge_kernel(const float* __restrict__ x,
                                                    const float* __restrict__ embed,
                                                    float* __restrict__ out,
                                                    long long out_size) {
    const int warp = threadIdx.x >> 5, lane = threadIdx.x & 31;
    const int t = blockIdx.x * 8 + warp;

    ulonglong4 v = g_top4[(size_t)lane * NT + t];   // 32 slices == 32 lanes

    // approx best over all 128 candidates (v.x is slice max)
    unsigned long long m = v.x;
    #pragma unroll
    for (int o = 16; o > 0; o >>= 1) {
        unsigned long long mo = __shfl_xor_sync(0xffffffffu, m, o);
        if (mo > m) m = mo;
    }
    const float thr = unpack_score(m) - MARGIN;

    const float4* xr4 = (const float4*)(x + (size_t)t * D);

    // x_sq for the loss (strided; only feeds the mean -> rounding harmless)
    float xs = 0.f;
    #pragma unroll
    for (int i = 0; i < 10; i++) {
        float4 a = xr4[lane + i * 32];
        xs += a.x * a.x + a.y * a.y + a.z * a.z + a.w * a.w;
    }
    #pragma unroll
    for (int o = 16; o > 0; o >>= 1) xs += __shfl_xor_sync(0xffffffffu, xs, o);

    // rescore in-margin candidates, one lane each, R1-exact arithmetic
    unsigned long long bestKey = 0ull;
    unsigned long long cand[4] = {v.x, v.y, v.z, v.w};
    #pragma unroll
    for (int slot = 0; slot < 4; slot++) {
        bool act = (unpack_score(cand[slot]) >= thr);   // NaN(empty) -> false
        if (__ballot_sync(0xffffffffu, act)) {
            if (act) {
                int idx = (int)(0xFFFFFFFFu - (uint32_t)cand[slot]);
                const float4* er4 = (const float4*)(embed + (size_t)idx * D);
                float d = 0.f;
                for (int i = 0; i < D / 4; i++) {       // strict ascending k
                    float4 a = xr4[i];
                    float4 b = er4[i];
                    d = fmaf(a.x, b.x, d);
                    d = fmaf(a.y, b.y, d);
                    d = fmaf(a.z, b.z, d);
                    d = fmaf(a.w, b.w, d);
                }
                float s = 2.0f * d - g_esq[idx];        // same form as R1
                unsigned long long k = pack_key(s, idx);
                if (k > bestKey) bestKey = k;
            }
        }
    }
    #pragma unroll
    for (int o = 16; o > 0; o >>= 1) {
        unsigned long long ko = __shfl_xor_sync(0xffffffffu, bestKey, o);
        if (ko > bestKey) bestKey = ko;
    }
    const int bestI = (int)(0xFFFFFFFFu - (uint32_t)bestKey);
    const float bestS = unpack_score(bestKey);

    if (lane == 0) {
        if (out_size >= (long long)NT * D + NT)
            out[(size_t)NT * D + t] = (float)bestI;
        atomicAdd(&g_loss, xs - bestS);
    }
    const float4* er = (const float4*)(embed + (size_t)bestI * D);
    float4* o = (float4*)(out + (size_t)t * D);
    #pragma unroll
    for (int i = 0; i < 10; i++) o[lane + i * 32] = er[lane + i * 32];
}

__global__ void loss_kernel(float* __restrict__ out, long long out_size) {
    if (out_size >= (long long)NT * D + NT + 1)
        out[(size_t)NT * D + NT] = g_loss / (float)((long long)NT * D);
}

// ---------------------------------------------------------------------------
extern "C" void kernel_launch(void* const* d_in, const int* in_sizes, int n_in,
                              void* d_out, int out_size) {
    const float* x     = (const float*)d_in[0];
    const float* embed = (const float*)d_in[1];
    float* out = (float*)d_out;

    static int smem_set = 0;
    if (!smem_set) {
        cudaFuncSetAttribute(gemm_kernel, cudaFuncAttributeMaxDynamicSharedMemorySize, SMEM_SZ);
        smem_set = 1;
    }

    __nv_bfloat16* gA;
    __nv_bfloat16* gB;
    cudaGetSymbolAddress((void**)&gA, g_A);
    cudaGetSymbolAddress((void**)&gB, g_B);

    conv_kernel<<<(NT * D / 8 + 255) / 256, 256>>>(x, gA, NT * D / 8);
    conv_kernel<<<(NC * D / 8 + 255) / 256, 256>>>(embed, gB, NC * D / 8);
    prep_kernel<<<NC, 128>>>(embed);
    gemm_kernel<<<dim3(N_TILES, M_TILES), 256, SMEM_SZ>>>();
    merge_kernel<<<NT / 8, 256>>>(x, embed, out, (long long)out_size);
    loss_kernel<<<1, 1>>>(out, (long long)out_size);
}

// round 7
// speedup vs baseline: 5.1401x; 1.0493x over previous
#include <cuda_runtime.h>
#include <cuda_bf16.h>
#include <cstdint>

// EuclideanCodebook on GB300 (base sm_103 target -> no tcgen05):
//   bf16 HMMA screening GEMM (BK=64, SW128, 3-stage cp.async) -> per-slice
//   top-4 -> margin rescore with R1-exact sequential-k fp32 fma chain ->
//   gather + loss.
//
//  x:     (32768, 1280) fp32   d_in[0]
//  embed: (4096, 1280)  fp32   d_in[1]
//  out:   [quantized 32768*1280 | indices 32768 | loss 1] fp32

#define NT 32768
#define D  1280
#define NC 4096

#define BM 128
#define BN 128
#define BK 64                    // bf16 elems per k-stage (128 B rows, SW128)
#define KITERS (D / BK)          // 20
#define N_TILES (NC / BN)        // 32
#define M_TILES (NT / BM)        // 256
#define MARGIN 6.0e-3f

// ---------------- static device scratch ----------------
__device__ __nv_bfloat16 g_A[(size_t)NT * D];        // 84 MB
__device__ __nv_bfloat16 g_B[(size_t)NC * D];        // 10.5 MB
__device__ float g_esq[NC];
__device__ ulonglong4 g_top4[(size_t)N_TILES * NT];  // 33.5 MB
__device__ float g_loss;

// ---------------- smem layout (dynamic) ----------------
#define STAGE_SZ  32768                  // A 16KB + B 16KB
#define OFF_A(s)  ((s) * STAGE_SZ)
#define OFF_B(s)  ((s) * STAGE_SZ + 16384)
#define SC_PITCH  137                    // score buffer aliases stage smem
#define OFF_ESQ   (3 * STAGE_SZ)         // 98304
#define SMEM_SZ   (OFF_ESQ + BN * 4)     // 98816  (x2 CTA = 197632 <= 228KB)

// ---------------- PTX helpers ----------------
__device__ __forceinline__ uint32_t smem_u32(const void* p) {
    uint32_t a;
    asm("{ .reg .u64 t; cvta.to.shared.u64 t, %1; cvt.u32.u64 %0, t; }"
        : "=r"(a) : "l"(p));
    return a;
}
__device__ __forceinline__ void cpasync16(uint32_t sa, const void* g) {
    asm volatile("cp.async.cg.shared.global [%0], [%1], 16;" :: "r"(sa), "l"(g));
}
#define CP_COMMIT() asm volatile("cp.async.commit_group;" ::: "memory")
#define CP_WAIT1()  asm volatile("cp.async.wait_group 1;" ::: "memory")
#define CP_WAIT0()  asm volatile("cp.async.wait_group 0;" ::: "memory")

__device__ __forceinline__ void ldm_x4(uint32_t* r, uint32_t addr) {
    asm volatile("ldmatrix.sync.aligned.m8n8.x4.shared.b16 {%0,%1,%2,%3}, [%4];"
                 : "=r"(r[0]), "=r"(r[1]), "=r"(r[2]), "=r"(r[3]) : "r"(addr));
}
__device__ __forceinline__ void mma_bf16(float* d, const uint32_t* a,
                                         uint32_t b0, uint32_t b1) {
    asm volatile("mma.sync.aligned.m16n8k16.row.col.f32.bf16.bf16.f32 "
                 "{%0,%1,%2,%3}, {%4,%5,%6,%7}, {%8,%9}, {%0,%1,%2,%3};"
                 : "+f"(d[0]), "+f"(d[1]), "+f"(d[2]), "+f"(d[3])
                 : "r"(a[0]), "r"(a[1]), "r"(a[2]), "r"(a[3]), "r"(b0), "r"(b1));
}

__device__ __forceinline__ unsigned long long pack_key(float s, int idx) {
    uint32_t fb = __float_as_uint(s);
    uint32_t key = (fb & 0x80000000u) ? ~fb : (fb | 0x80000000u);
    return ((unsigned long long)key << 32) |
           (unsigned long long)(0xFFFFFFFFu - (uint32_t)idx);
}
__device__ __forceinline__ float unpack_score(unsigned long long pk) {
    uint32_t k = (uint32_t)(pk >> 32);
    return __uint_as_float((k & 0x80000000u) ? (k ^ 0x80000000u) : ~k);
}

// ---------------------------------------------------------------------------
// fp32 -> bf16 staging
// ---------------------------------------------------------------------------
__global__ void conv_kernel(const float* __restrict__ src,
                            __nv_bfloat16* __restrict__ dst, int n8) {
    int i = blockIdx.x * blockDim.x + threadIdx.x;
    if (i >= n8) return;
    const float4* s = (const float4*)src + (size_t)i * 2;
    float4 a = s[0], b = s[1];
    __nv_bfloat162 h0 = __float22bfloat162_rn(make_float2(a.x, a.y));
    __nv_bfloat162 h1 = __float22bfloat162_rn(make_float2(a.z, a.w));
    __nv_bfloat162 h2 = __float22bfloat162_rn(make_float2(b.x, b.y));
    __nv_bfloat162 h3 = __float22bfloat162_rn(make_float2(b.z, b.w));
    uint4 v;
    v.x = *(uint32_t*)&h0; v.y = *(uint32_t*)&h1;
    v.z = *(uint32_t*)&h2; v.w = *(uint32_t*)&h3;
    ((uint4*)dst)[i] = v;
}

// ---------------------------------------------------------------------------
// prep: exact e_sq per code + loss init
// ---------------------------------------------------------------------------
__global__ void prep_kernel(const float* __restrict__ embed) {
    const int code = blockIdx.x;
    const float4* e = (const float4*)(embed + (size_t)code * D);
    float s = 0.f;
    for (int i = threadIdx.x; i < D / 4; i += blockDim.x) {
        float4 v = e[i];
        s += v.x * v.x + v.y * v.y + v.z * v.z + v.w * v.w;
    }
    #pragma unroll
    for (int o = 16; o > 0; o >>= 1) s += __shfl_down_sync(0xffffffffu, s, o);
    __shared__ float red[4];
    if ((threadIdx.x & 31) == 0) red[threadIdx.x >> 5] = s;
    __syncthreads();
    if (threadIdx.x == 0) {
        g_esq[code] = red[0] + red[1] + red[2] + red[3];
        if (code == 0) g_loss = 0.f;
    }
}

// ---------------------------------------------------------------------------
// HMMA bf16 GEMM + per-slice top-4
// grid (N_TILES, M_TILES) x 256 threads. Warp 2x4: warp tile 64(m) x 32(n).
// ---------------------------------------------------------------------------
__global__ __launch_bounds__(256, 2) void gemm_kernel() {
    extern __shared__ char smem[];
    const uint32_t sb = smem_u32(smem);
    const int tid = threadIdx.x;
    const int warp = tid >> 5, lane = tid & 31;
    const int warp_m = warp >> 2, warp_n = warp & 3;
    const int codeBase = blockIdx.x * BN;
    const int tokBase  = blockIdx.y * BM;

    float* esq_s = (float*)(smem + OFF_ESQ);
    if (tid < BN) esq_s[tid] = g_esq[codeBase + tid];

    const __nv_bfloat16* Abase = g_A + (size_t)tokBase * D;
    const __nv_bfloat16* Bbase = g_B + (size_t)codeBase * D;

    // stage store mapping: instr j covers rows j*32+(tid>>3), chunk tid&7.
    // Warp per instr = 4 full 128B rows (perfect sectors), SW128 swizzled.
    int soff[4];
    long goff[4];
    #pragma unroll
    for (int j = 0; j < 4; j++) {
        int row = j * 32 + (tid >> 3);
        int chunk = tid & 7;
        soff[j] = row * 128 + ((chunk ^ (row & 7)) << 4);
        goff[j] = (long)row * D + chunk * 8;
    }

    auto load_stage = [&](int kt, int slot) {
        const uint32_t ab = sb + OFF_A(slot), bb = sb + OFF_B(slot);
        const __nv_bfloat16* Ak = Abase + kt * BK;
        const __nv_bfloat16* Bk = Bbase + kt * BK;
        #pragma unroll
        for (int j = 0; j < 4; j++) {
            cpasync16(ab + soff[j], Ak + goff[j]);
            cpasync16(bb + soff[j], Bk + goff[j]);
        }
    };

    // ldmatrix address pieces (SW128: xor by row&7 == l15&7)
    const int l15 = lane & 15;
    const int colsel = lane >> 4;
    const int sw = l15 & 7;
    uint32_t aRow[4], bRow[2], ckx[4];
    #pragma unroll
    for (int mt = 0; mt < 4; mt++) aRow[mt] = (warp_m * 64 + mt * 16 + l15) * 128;
    #pragma unroll
    for (int nh = 0; nh < 2; nh++) bRow[nh] = (warp_n * 32 + nh * 16 + l15) * 128;
    #pragma unroll
    for (int kh = 0; kh < 4; kh++) ckx[kh] = (uint32_t)(((2 * kh + colsel) ^ sw) << 4);

    float acc[4][4][4];
    #pragma unroll
    for (int mt = 0; mt < 4; mt++)
        #pragma unroll
        for (int nt = 0; nt < 4; nt++)
            #pragma unroll
            for (int i = 0; i < 4; i++) acc[mt][nt][i] = 0.f;

    load_stage(0, 0); CP_COMMIT();
    load_stage(1, 1); CP_COMMIT();

    int s0 = 0, s2 = 2;
    for (int kt = 0; kt < KITERS; kt++) {
        CP_WAIT1();
        __syncthreads();
        if (kt + 2 < KITERS) load_stage(kt + 2, s2);
        CP_COMMIT();                       // empty at tail keeps wait semantics
        const uint32_t ab = sb + OFF_A(s0), bb = sb + OFF_B(s0);
        #pragma unroll
        for (int kh = 0; kh < 4; kh++) {
            uint32_t a[4][4], b[2][4];
            #pragma unroll
            for (int mt = 0; mt < 4; mt++) ldm_x4(a[mt], ab + aRow[mt] + ckx[kh]);
            #pragma unroll
            for (int nh = 0; nh < 2; nh++) ldm_x4(b[nh], bb + bRow[nh] + ckx[kh]);
            #pragma unroll
            for (int mt = 0; mt < 4; mt++)
                #pragma unroll
                for (int nt = 0; nt < 4; nt++)
                    mma_bf16(acc[mt][nt], a[mt], b[nt >> 1][nt & 1], b[nt >> 1][(nt & 1) + 2]);
        }
        if (++s0 == 3) s0 = 0;
        if (++s2 == 3) s2 = 0;
    }
    CP_WAIT0();
    __syncthreads();   // stage buffers dead -> reuse as score buffer

    // scores -> smem [128][SC_PITCH]
    float* sc = (float*)smem;
    const int rq = lane >> 2;
    const int cq = (lane & 3) * 2;
    #pragma unroll
    for (int mt = 0; mt < 4; mt++) {
        const int r = warp_m * 64 + mt * 16 + rq;
        #pragma unroll
        for (int nt = 0; nt < 4; nt++) {
            const int c = warp_n * 32 + nt * 8 + cq;
            sc[r * SC_PITCH + c]           = 2.f * acc[mt][nt][0] - esq_s[c];
            sc[r * SC_PITCH + c + 1]       = 2.f * acc[mt][nt][1] - esq_s[c + 1];
            sc[(r + 8) * SC_PITCH + c]     = 2.f * acc[mt][nt][2] - esq_s[c];
            sc[(r + 8) * SC_PITCH + c + 1] = 2.f * acc[mt][nt][3] - esq_s[c + 1];
        }
    }
    __syncthreads();

    // one thread per token: packed top-4 over this 128-code slice
    if (tid < BM) {
        const float* row = sc + tid * SC_PITCH;
        unsigned long long t0 = 0ull, t1 = 0ull, t2 = 0ull, t3 = 0ull;
        #pragma unroll 4
        for (int j = 0; j < BN; j++) {
            unsigned long long pk = pack_key(row[j], codeBase + j);
            if (pk > t0)      { t3 = t2; t2 = t1; t1 = t0; t0 = pk; }
            else if (pk > t1) { t3 = t2; t2 = t1; t1 = pk; }
            else if (pk > t2) { t3 = t2; t2 = pk; }
            else if (pk > t3) { t3 = pk; }
        }
        g_top4[(size_t)blockIdx.x * NT + tokBase + tid] =
            make_ulonglong4(t0, t1, t2, t3);
    }
}

// ---------------------------------------------------------------------------
// merge + R1-exact sequential-k fp32 rescore + gather + loss; warp per token.
// ---------------------------------------------------------------------------
__global__ __launch_bounds__(256) void merge_kernel(const float* __restrict__ x,
                                                    const float* __restrict__ embed,
                                                    float* __restrict__ out,
                                                    long long out_size) {
    const int warp = threadIdx.x >> 5, lane = threadIdx.x & 31;
    const int t = blockIdx.x * 8 + warp;

    ulonglong4 v = g_top4[(size_t)lane * NT + t];   // 32 slices == 32 lanes

    unsigned long long m = v.x;
    #pragma unroll
    for (int o = 16; o > 0; o >>= 1) {
        unsigned long long mo = __shfl_xor_sync(0xffffffffu, m, o);
        if (mo > m) m = mo;
    }
    const float thr = unpack_score(m) - MARGIN;

    const float4* xr4 = (const float4*)(x + (size_t)t * D);

    float xs = 0.f;
    #pragma unroll
    for (int i = 0; i < 10; i++) {
        float4 a = xr4[lane + i * 32];
        xs += a.x * a.x + a.y * a.y + a.z * a.z + a.w * a.w;
    }
    #pragma unroll
    for (int o = 16; o > 0; o >>= 1) xs += __shfl_xor_sync(0xffffffffu, xs, o);

    unsigned long long bestKey = 0ull;
    unsigned long long cand[4] = {v.x, v.y, v.z, v.w};
    #pragma unroll
    for (int slot = 0; slot < 4; slot++) {
        bool act = (unpack_score(cand[slot]) >= thr);
        if (__ballot_sync(0xffffffffu, act)) {
            if (act) {
                int idx = (int)(0xFFFFFFFFu - (uint32_t)cand[slot]);
                const float4* er4 = (const float4*)(embed + (size_t)idx * D);
                float d = 0.f;
                for (int i = 0; i < D / 4; i++) {       // strict ascending k
                    float4 a = xr4[i];
                    float4 b = er4[i];
                    d = fmaf(a.x, b.x, d);
                    d = fmaf(a.y, b.y, d);
                    d = fmaf(a.z, b.z, d);
                    d = fmaf(a.w, b.w, d);
                }
                float s = 2.0f * d - g_esq[idx];
                unsigned long long k = pack_key(s, idx);
                if (k > bestKey) bestKey = k;
            }
        }
    }
    #pragma unroll
    for (int o = 16; o > 0; o >>= 1) {
        unsigned long long ko = __shfl_xor_sync(0xffffffffu, bestKey, o);
        if (ko > bestKey) bestKey = ko;
    }
    const int bestI = (int)(0xFFFFFFFFu - (uint32_t)bestKey);
    const float bestS = unpack_score(bestKey);

    if (lane == 0) {
        if (out_size >= (long long)NT * D + NT)
            out[(size_t)NT * D + t] = (float)bestI;
        atomicAdd(&g_loss, xs - bestS);
    }
    const float4* er = (const float4*)(embed + (size_t)bestI * D);
    float4* o = (float4*)(out + (size_t)t * D);
    #pragma unroll
    for (int i = 0; i < 10; i++) o[lane + i * 32] = er[lane + i * 32];
}

__global__ void loss_kernel(float* __restrict__ out, long long out_size) {
    if (out_size >= (long long)NT * D + NT + 1)
        out[(size_t)NT * D + NT] = g_loss / (float)((long long)NT * D);
}

// ---------------------------------------------------------------------------
extern "C" void kernel_launch(void* const* d_in, const int* in_sizes, int n_in,
                              void* d_out, int out_size) {
    const float* x     = (const float*)d_in[0];
    const float* embed = (const float*)d_in[1];
    float* out = (float*)d_out;

    static int smem_set = 0;
    if (!smem_set) {
        cudaFuncSetAttribute(gemm_kernel, cudaFuncAttributeMaxDynamicSharedMemorySize, SMEM_SZ);
        smem_set = 1;
    }

    __nv_bfloat16* gA;
    __nv_bfloat16* gB;
    cudaGetSymbolAddress((void**)&gA, g_A);
    cudaGetSymbolAddress((void**)&gB, g_B);

    conv_kernel<<<(NT * D / 8 + 255) / 256, 256>>>(x, gA, NT * D / 8);
    conv_kernel<<<(NC * D / 8 + 255) / 256, 256>>>(embed, gB, NC * D / 8);
    prep_kernel<<<NC, 128>>>(embed);
    gemm_kernel<<<dim3(N_TILES, M_TILES), 256, SMEM_SZ>>>();
    merge_kernel<<<NT / 8, 256>>>(x, embed, out, (long long)out_size);
    loss_kernel<<<1, 1>>>(out, (long long)out_size);
}

// round 8
// speedup vs baseline: 5.2116x; 1.0139x over previous
#include <cuda_runtime.h>
#include <cuda_bf16.h>
#include <cstdint>

// EuclideanCodebook on GB300 (base sm_103 target):
//   pre-tiled/pre-swizzled bf16 layout -> cp.async.bulk (2 DMA per stage)
//   -> HMMA mma.sync GEMM -> per-slice top-4 -> R1-exact fp32 rescore.
//
//  x:     (32768, 1280) fp32   d_in[0]
//  embed: (4096, 1280)  fp32   d_in[1]
//  out:   [quantized 32768*1280 | indices 32768 | loss 1] fp32

#define NT 32768
#define D  1280
#define NC 4096

#define BM 128
#define BN 128
#define BK 64                    // bf16 per k-stage (one 16KB block per matrix)
#define KITERS (D / BK)          // 20
#define N_TILES (NC / BN)        // 32
#define M_TILES (NT / BM)        // 256
#define MARGIN 6.0e-3f
#define TILE_BYTES (BM * BK * 2) // 16384
#define CHUNKS (D / 8)           // 160 16B-chunks per row

// ---------------- static device scratch ----------------
// staged layouts: [tile][kt][row 128][chunk perm]  (16KB contiguous blocks)
__device__ __align__(128) unsigned char g_A[(size_t)NT * D * 2];  // 84 MB
__device__ __align__(128) unsigned char g_B[(size_t)NC * D * 2];  // 10.5 MB
__device__ float g_esq[NC];
__device__ ulonglong4 g_top4[(size_t)N_TILES * NT];               // 33.5 MB
__device__ float g_loss;

// ---------------- smem layout (dynamic) ----------------
#define STAGE_SZ  32768                  // A 16KB + B 16KB
#define OFF_A(s)  ((s) * STAGE_SZ)
#define OFF_B(s)  ((s) * STAGE_SZ + 16384)
#define SC_PITCH  137                    // score buffer aliases stage smem
#define OFF_ESQ   (3 * STAGE_SZ)         // 98304
#define OFF_MBAR  (OFF_ESQ + 512)        // 3 mbarriers
#define SMEM_SZ   (OFF_MBAR + 64)        // 98880 (x2 CTA <= 228KB)

// ---------------- PTX helpers ----------------
__device__ __forceinline__ uint32_t smem_u32(const void* p) {
    uint32_t a;
    asm("{ .reg .u64 t; cvta.to.shared.u64 t, %1; cvt.u32.u64 %0, t; }"
        : "=r"(a) : "l"(p));
    return a;
}
#define MBAR_INIT(mb, n) \
    asm volatile("mbarrier.init.shared.b64 [%0], %1;" :: "r"((uint32_t)(mb)), "r"((uint32_t)(n)) : "memory")
#define MBAR_EXPECT(mb, bytes) \
    asm volatile("mbarrier.arrive.expect_tx.shared.b64 _, [%0], %1;" \
                 :: "r"((uint32_t)(mb)), "r"((uint32_t)(bytes)) : "memory")
#define MBAR_WAIT(mb, ph) do {                                                          \
    uint32_t _m = (uint32_t)(mb), _p = (uint32_t)(ph), _d;                              \
    asm volatile("{ .reg .pred p; mbarrier.try_wait.parity.shared.b64 p, [%1], %2;"     \
                 " selp.b32 %0,1,0,p; }" : "=r"(_d) : "r"(_m), "r"(_p) : "memory");     \
    if (!_d) {                                                                          \
        asm volatile("{ .reg .pred P1; WL_%=: mbarrier.try_wait.parity.shared.b64 P1, [%0], %1;" \
                     " @P1 bra.uni WD_%=; bra.uni WL_%=; WD_%=: }"                      \
                     :: "r"(_m), "r"(_p) : "memory");                                   \
    } } while (0)
__device__ __forceinline__ void bulk_g2s(uint32_t dst, const void* src,
                                         uint32_t bytes, uint32_t mbar) {
    asm volatile("cp.async.bulk.shared::cluster.global.mbarrier::complete_tx::bytes "
                 "[%0], [%1], %2, [%3];"
                 :: "r"(dst), "l"(src), "r"(bytes), "r"(mbar) : "memory");
}

__device__ __forceinline__ void ldm_x4(uint32_t* r, uint32_t addr) {
    asm volatile("ldmatrix.sync.aligned.m8n8.x4.shared.b16 {%0,%1,%2,%3}, [%4];"
                 : "=r"(r[0]), "=r"(r[1]), "=r"(r[2]), "=r"(r[3]) : "r"(addr));
}
__device__ __forceinline__ void mma_bf16(float* d, const uint32_t* a,
                                         uint32_t b0, uint32_t b1) {
    asm volatile("mma.sync.aligned.m16n8k16.row.col.f32.bf16.bf16.f32 "
                 "{%0,%1,%2,%3}, {%4,%5,%6,%7}, {%8,%9}, {%0,%1,%2,%3};"
                 : "+f"(d[0]), "+f"(d[1]), "+f"(d[2]), "+f"(d[3])
                 : "r"(a[0]), "r"(a[1]), "r"(a[2]), "r"(a[3]), "r"(b0), "r"(b1));
}

__device__ __forceinline__ unsigned long long pack_key(float s, int idx) {
    uint32_t fb = __float_as_uint(s);
    uint32_t key = (fb & 0x80000000u) ? ~fb : (fb | 0x80000000u);
    return ((unsigned long long)key << 32) |
           (unsigned long long)(0xFFFFFFFFu - (uint32_t)idx);
}
__device__ __forceinline__ float unpack_score(unsigned long long pk) {
    uint32_t k = (uint32_t)(pk >> 32);
    return __uint_as_float((k & 0x80000000u) ? (k ^ 0x80000000u) : ~k);
}

// ---------------------------------------------------------------------------
// fp32 -> bf16 staging into tiled/swizzled layout.
// chunk i: token t = i/CHUNKS, c = i%CHUNKS; kt = c>>3, ch = c&7.
// dst = base + ((tile*KITERS + kt)<<14) + (row<<7) + ((ch ^ (row&7))<<4)
// ---------------------------------------------------------------------------
__global__ void conv_kernel(const float* __restrict__ src,
                            unsigned char* __restrict__ dst, int nchunks) {
    int i = blockIdx.x * blockDim.x + threadIdx.x;
    if (i >= nchunks) return;
    const int t = i / CHUNKS, c = i - t * CHUNKS;
    const int kt = c >> 3, ch = c & 7;
    const int row = t & 127, tile = t >> 7;

    const float4* s = (const float4*)(src + (size_t)t * D + c * 8);
    float4 a = s[0], b = s[1];
    __nv_bfloat162 h0 = __float22bfloat162_rn(make_float2(a.x, a.y));
    __nv_bfloat162 h1 = __float22bfloat162_rn(make_float2(a.z, a.w));
    __nv_bfloat162 h2 = __float22bfloat162_rn(make_float2(b.x, b.y));
    __nv_bfloat162 h3 = __float22bfloat162_rn(make_float2(b.z, b.w));
    uint4 v;
    v.x = *(uint32_t*)&h0; v.y = *(uint32_t*)&h1;
    v.z = *(uint32_t*)&h2; v.w = *(uint32_t*)&h3;

    size_t off = ((size_t)(tile * KITERS + kt) << 14) + (row << 7)
               + ((ch ^ (row & 7)) << 4);
    *(uint4*)(dst + off) = v;
}

// ---------------------------------------------------------------------------
// prep: exact e_sq per code + loss init
// ---------------------------------------------------------------------------
__global__ void prep_kernel(const float* __restrict__ embed) {
    const int code = blockIdx.x;
    const float4* e = (const float4*)(embed + (size_t)code * D);
    float s = 0.f;
    for (int i = threadIdx.x; i < D / 4; i += blockDim.x) {
        float4 v = e[i];
        s += v.x * v.x + v.y * v.y + v.z * v.z + v.w * v.w;
    }
    #pragma unroll
    for (int o = 16; o > 0; o >>= 1) s += __shfl_down_sync(0xffffffffu, s, o);
    __shared__ float red[4];
    if ((threadIdx.x & 31) == 0) red[threadIdx.x >> 5] = s;
    __syncthreads();
    if (threadIdx.x == 0) {
        g_esq[code] = red[0] + red[1] + red[2] + red[3];
        if (code == 0) g_loss = 0.f;
    }
}

// ---------------------------------------------------------------------------
// HMMA bf16 GEMM (bulk-DMA staged) + per-slice top-4
// grid (N_TILES, M_TILES) x 256 threads. Warp 2x4: warp tile 64(m) x 32(n).
// ---------------------------------------------------------------------------
__global__ __launch_bounds__(256, 2) void gemm_kernel() {
    extern __shared__ char smem[];
    const uint32_t sb = smem_u32(smem);
    const int tid = threadIdx.x;
    const int warp = tid >> 5, lane = tid & 31;
    const int warp_m = warp >> 2, warp_n = warp & 3;
    const int codeBase = blockIdx.x * BN;
    const int tokBase  = blockIdx.y * BM;

    float* esq_s = (float*)(smem + OFF_ESQ);
    if (tid < BN) esq_s[tid] = g_esq[codeBase + tid];

    const unsigned char* Ab = g_A + ((size_t)blockIdx.y * KITERS << 14);
    const unsigned char* Bb = g_B + ((size_t)blockIdx.x * KITERS << 14);

    if (tid == 0) {
        #pragma unroll
        for (int s = 0; s < 3; s++) MBAR_INIT(sb + OFF_MBAR + s * 8, 1);
    }
    __syncthreads();

    // prologue: stages 0,1 in flight
    if (tid == 0) {
        #pragma unroll
        for (int s = 0; s < 2; s++) {
            MBAR_EXPECT(sb + OFF_MBAR + s * 8, STAGE_SZ);
            bulk_g2s(sb + OFF_A(s), Ab + ((size_t)s << 14), TILE_BYTES,
                     sb + OFF_MBAR + s * 8);
            bulk_g2s(sb + OFF_B(s), Bb + ((size_t)s << 14), TILE_BYTES,
                     sb + OFF_MBAR + s * 8);
        }
    }

    // ldmatrix address pieces (SW128: xor by row&7 == l15&7)
    const int l15 = lane & 15;
    const int colsel = lane >> 4;
    const int sw = l15 & 7;
    uint32_t aRow[4], bRow[2], ckx[4];
    #pragma unroll
    for (int mt = 0; mt < 4; mt++) aRow[mt] = (warp_m * 64 + mt * 16 + l15) * 128;
    #pragma unroll
    for (int nh = 0; nh < 2; nh++) bRow[nh] = (warp_n * 32 + nh * 16 + l15) * 128;
    #pragma unroll
    for (int kh = 0; kh < 4; kh++) ckx[kh] = (uint32_t)(((2 * kh + colsel) ^ sw) << 4);

    float acc[4][4][4];
    #pragma unroll
    for (int mt = 0; mt < 4; mt++)
        #pragma unroll
        for (int nt = 0; nt < 4; nt++)
            #pragma unroll
            for (int i = 0; i < 4; i++) acc[mt][nt][i] = 0.f;

    int slot = 0, slot2 = 2;
    int phase[3] = {0, 0, 0};
    for (int kt = 0; kt < KITERS; kt++) {
        __syncthreads();                   // all warps done reading slot2's old data
        if (kt + 2 < KITERS && tid == 0) {
            MBAR_EXPECT(sb + OFF_MBAR + slot2 * 8, STAGE_SZ);
            bulk_g2s(sb + OFF_A(slot2), Ab + ((size_t)(kt + 2) << 14), TILE_BYTES,
                     sb + OFF_MBAR + slot2 * 8);
            bulk_g2s(sb + OFF_B(slot2), Bb + ((size_t)(kt + 2) << 14), TILE_BYTES,
                     sb + OFF_MBAR + slot2 * 8);
        }
        MBAR_WAIT(sb + OFF_MBAR + slot * 8, phase[slot]);
        phase[slot] ^= 1;

        const uint32_t ab = sb + OFF_A(slot), bb = sb + OFF_B(slot);
        #pragma unroll
        for (int kh = 0; kh < 4; kh++) {
            uint32_t a[4][4], b[2][4];
            #pragma unroll
            for (int mt = 0; mt < 4; mt++) ldm_x4(a[mt], ab + aRow[mt] + ckx[kh]);
            #pragma unroll
            for (int nh = 0; nh < 2; nh++) ldm_x4(b[nh], bb + bRow[nh] + ckx[kh]);
            #pragma unroll
            for (int mt = 0; mt < 4; mt++)
                #pragma unroll
                for (int nt = 0; nt < 4; nt++)
                    mma_bf16(acc[mt][nt], a[mt], b[nt >> 1][nt & 1], b[nt >> 1][(nt & 1) + 2]);
        }
        if (++slot == 3) slot = 0;
        if (++slot2 == 3) slot2 = 0;
    }
    __syncthreads();   // stage buffers dead -> reuse as score buffer

    // scores -> smem [128][SC_PITCH]
    float* sc = (float*)smem;
    const int rq = lane >> 2;
    const int cq = (lane & 3) * 2;
    #pragma unroll
    for (int mt = 0; mt < 4; mt++) {
        const int r = warp_m * 64 + mt * 16 + rq;
        #pragma unroll
        for (int nt = 0; nt < 4; nt++) {
            const int c = warp_n * 32 + nt * 8 + cq;
            sc[r * SC_PITCH + c]           = 2.f * acc[mt][nt][0] - esq_s[c];
            sc[r * SC_PITCH + c + 1]       = 2.f * acc[mt][nt][1] - esq_s[c + 1];
            sc[(r + 8) * SC_PITCH + c]     = 2.f * acc[mt][nt][2] - esq_s[c];
            sc[(r + 8) * SC_PITCH + c + 1] = 2.f * acc[mt][nt][3] - esq_s[c + 1];
        }
    }
    __syncthreads();

    // one thread per token: packed top-4 over this 128-code slice
    if (tid < BM) {
        const float* row = sc + tid * SC_PITCH;
        unsigned long long t0 = 0ull, t1 = 0ull, t2 = 0ull, t3 = 0ull;
        #pragma unroll 4
        for (int j = 0; j < BN; j++) {
            unsigned long long pk = pack_key(row[j], codeBase + j);
            if (pk > t0)      { t3 = t2; t2 = t1; t1 = t0; t0 = pk; }
            else if (pk > t1) { t3 = t2; t2 = t1; t1 = pk; }
            else if (pk > t2) { t3 = t2; t2 = pk; }
            else if (pk > t3) { t3 = pk; }
        }
        g_top4[(size_t)blockIdx.x * NT + tokBase + tid] =
            make_ulonglong4(t0, t1, t2, t3);
    }
}

// ---------------------------------------------------------------------------
// merge + R1-exact sequential-k fp32 rescore + gather + loss; warp per token.
// ---------------------------------------------------------------------------
__global__ __launch_bounds__(256) void merge_kernel(const float* __restrict__ x,
                                                    const float* __restrict__ embed,
                                                    float* __restrict__ out,
                                                    long long out_size) {
    const int warp = threadIdx.x >> 5, lane = threadIdx.x & 31;
    const int t = blockIdx.x * 8 + warp;

    ulonglong4 v = g_top4[(size_t)lane * NT + t];   // 32 slices == 32 lanes

    unsigned long long m = v.x;
    #pragma unroll
    for (int o = 16; o > 0; o >>= 1) {
        unsigned long long mo = __shfl_xor_sync(0xffffffffu, m, o);
        if (mo > m) m = mo;
    }
    const float thr = unpack_score(m) - MARGIN;

    const float4* xr4 = (const float4*)(x + (size_t)t * D);

    float xs = 0.f;
    #pragma unroll
    for (int i = 0; i < 10; i++) {
        float4 a = xr4[lane + i * 32];
        xs += a.x * a.x + a.y * a.y + a.z * a.z + a.w * a.w;
    }
    #pragma unroll
    for (int o = 16; o > 0; o >>= 1) xs += __shfl_xor_sync(0xffffffffu, xs, o);

    unsigned long long bestKey = 0ull;
    unsigned long long cand[4] = {v.x, v.y, v.z, v.w};
    #pragma unroll
    for (int slot = 0; slot < 4; slot++) {
        bool act = (unpack_score(cand[slot]) >= thr);
        if (__ballot_sync(0xffffffffu, act)) {
            if (act) {
                int idx = (int)(0xFFFFFFFFu - (uint32_t)cand[slot]);
                const float4* er4 = (const float4*)(embed + (size_t)idx * D);
                float d = 0.f;
                for (int i = 0; i < D / 4; i++) {       // strict ascending k
                    float4 a = xr4[i];
                    float4 b = er4[i];
                    d = fmaf(a.x, b.x, d);
                    d = fmaf(a.y, b.y, d);
                    d = fmaf(a.z, b.z, d);
                    d = fmaf(a.w, b.w, d);
                }
                float s = 2.0f * d - g_esq[idx];
                unsigned long long k = pack_key(s, idx);
                if (k > bestKey) bestKey = k;
            }
        }
    }
    #pragma unroll
    for (int o = 16; o > 0; o >>= 1) {
        unsigned long long ko = __shfl_xor_sync(0xffffffffu, bestKey, o);
        if (ko > bestKey) bestKey = ko;
    }
    const int bestI = (int)(0xFFFFFFFFu - (uint32_t)bestKey);
    const float bestS = unpack_score(bestKey);

    if (lane == 0) {
        if (out_size >= (long long)NT * D + NT)
            out[(size_t)NT * D + t] = (float)bestI;
        atomicAdd(&g_loss, xs - bestS);
    }
    const float4* er = (const float4*)(embed + (size_t)bestI * D);
    float4* o = (float4*)(out + (size_t)t * D);
    #pragma unroll
    for (int i = 0; i < 10; i++) o[lane + i * 32] = er[lane + i * 32];
}

__global__ void loss_kernel(float* __restrict__ out, long long out_size) {
    if (out_size >= (long long)NT * D + NT + 1)
        out[(size_t)NT * D + NT] = g_loss / (float)((long long)NT * D);
}

// ---------------------------------------------------------------------------
extern "C" void kernel_launch(void* const* d_in, const int* in_sizes, int n_in,
                              void* d_out, int out_size) {
    const float* x     = (const float*)d_in[0];
    const float* embed = (const float*)d_in[1];
    float* out = (float*)d_out;

    static int smem_set = 0;
    if (!smem_set) {
        cudaFuncSetAttribute(gemm_kernel, cudaFuncAttributeMaxDynamicSharedMemorySize, SMEM_SZ);
        smem_set = 1;
    }

    unsigned char* gA;
    unsigned char* gB;
    cudaGetSymbolAddress((void**)&gA, g_A);
    cudaGetSymbolAddress((void**)&gB, g_B);

    conv_kernel<<<(NT * CHUNKS + 255) / 256, 256>>>(x, gA, NT * CHUNKS);
    conv_kernel<<<(NC * CHUNKS + 255) / 256, 256>>>(embed, gB, NC * CHUNKS);
    prep_kernel<<<NC, 128>>>(embed);
    gemm_kernel<<<dim3(N_TILES, M_TILES), 256, SMEM_SZ>>>();
    merge_kernel<<<NT / 8, 256>>>(x, embed, out, (long long)out_size);
    loss_kernel<<<1, 1>>>(out, (long long)out_size);
}